// round 13
// baseline (speedup 1.0000x reference)
#include <cuda_runtime.h>
#include <cuda_bf16.h>
#include <stdint.h>

// Problem constants
#define BB   4
#define H    352
#define W    1216
#define HW   (H*W)               // 428032
#define NPX  (BB*HW)             // 1712128 pixels (divisible by 4)
#define PAD  2
#define HP   (H + 2*PAD)         // 356
#define WP   (W + 2*PAD)         // 1220
#define NPAD (BB*HP*WP)          // 1737280 < 2^21
#define PROP 18

typedef unsigned long long u64;

// Packed tap record (u64):
//  [0,21)   : padded linear index of top-left corner
//  [21,34)  : fy  (13-bit fraction, /8192)
//  [34,47)  : fx  (13-bit fraction, /8192)
//  [47,64)  : aff (17-bit fixed point, (q-65536)/32768)
// Stored as 4 planes of uint4 (two taps per 16B record) for LDG.128.

__device__ float g_buf[2][NPAD];          // scalar padded ping-pong feat (conf-folded)
__device__ uint4 d_meta[4 * NPX];

// ---------------------------------------------------------------------------
// Packed fp32x2 helpers (Blackwell dual-rate fp32 path; FFMA2 only via PTX)
__device__ __forceinline__ u64 pack2(float lo, float hi) {
    u64 r; asm("mov.b64 %0, {%1, %2};" : "=l"(r) : "f"(lo), "f"(hi)); return r;
}
__device__ __forceinline__ void unpack2(u64 v, float& lo, float& hi) {
    asm("mov.b64 {%0, %1}, %2;" : "=f"(lo), "=f"(hi) : "l"(v));
}
__device__ __forceinline__ u64 fma2(u64 a, u64 b, u64 c) {
    u64 d; asm("fma.rn.f32x2 %0, %1, %2, %3;" : "=l"(d) : "l"(a), "l"(b), "l"(c));
    return d;
}

// ---------------------------------------------------------------------------
__global__ void zero_kernel() {
    int i = blockIdx.x * blockDim.x + threadIdx.x;
    if (i < 2 * NPAD) (&g_buf[0][0])[i] = 0.0f;
}

__global__ void init_kernel(const float* __restrict__ feat,
                            const float* __restrict__ conf) {
    int p = blockIdx.x * blockDim.x + threadIdx.x;
    if (p >= NPX) return;
    int b = p / HW;
    int r = p - b * HW;
    int y = r / W;
    int x = r - y * W;
    int pidx = (b * HP + y + PAD) * WP + (x + PAD);
    g_buf[0][pidx] = feat[p] * conf[p];
}

// ---------------------------------------------------------------------------
__device__ __forceinline__ u64 encode_tap(
        int b, int y, int x, int j, float dy, float dx, float aff)
{
    float ys = (float)(y + j / 3 - 1) + dy;
    float xs = (float)(x + j % 3 - 1) + dx;
    float y0f = floorf(ys);
    float x0f = floorf(xs);
    float fy = ys - y0f;
    float fx = xs - x0f;
    int iy = (int)fmaxf(fminf(y0f, 1.0e6f), -1.0e6f);
    int ix = (int)fmaxf(fminf(x0f, 1.0e6f), -1.0e6f);
    // clamp into padded box; out-of-image corners land on guaranteed zeros
    int yp = min(max(iy + PAD, 0), HP - 2);
    int xp = min(max(ix + PAD, 0), WP - 2);
    u64 idx = (u64)((b * HP + yp) * WP + xp);
    int fu = (int)(fy * 8192.0f + 0.5f); fu = min(max(fu, 0), 8191);
    int fv = (int)(fx * 8192.0f + 0.5f); fv = min(max(fv, 0), 8191);
    int qa = (int)floorf(aff * 32768.0f + 0.5f) + 65536;
    qa = min(max(qa, 0), 131071);
    return idx | ((u64)fu << 21) | ((u64)fv << 34) | ((u64)qa << 47);
}

// Conv(8 -> 24, 3x3, pad 1) via packed f32x2 FFMA2; 2 pixels / thread
// (one lane-pair). Register-lean epilogue: encode+store per plane, no tmp
// arrays -> no spills (the 4px/thread version spilled heavily).
__global__ __launch_bounds__(256)
void conv_meta_kernel(const float* __restrict__ guid,
                      const float* __restrict__ w_oa,
                      const float* __restrict__ b_oa,
                      const float* __restrict__ aff_scale) {
    __shared__ u64   ws2[1728];
    __shared__ float bs[24];
    for (int i = threadIdx.x; i < 1728; i += blockDim.x) {
        float w = w_oa[i];
        ws2[i] = pack2(w, w);
    }
    if (threadIdx.x < 24) bs[threadIdx.x] = b_oa[threadIdx.x];
    __syncthreads();

    int t  = blockIdx.x * blockDim.x + threadIdx.x;
    int p0 = 2 * t;
    if (p0 >= NPX) return;
    int b = p0 / HW;
    int r = p0 - b * HW;
    int y = r / W;
    int x = r - y * W;   // x even (W even): both px same row

    u64 acc[24];         // lane pair = (px0, px1)
#pragma unroll
    for (int c = 0; c < 24; c++) acc[c] = pack2(bs[c], bs[c]);

    const float* gb = guid + (size_t)b * 8 * HW;
    for (int i = 0; i < 8; i++) {
        const float* gch = gb + i * HW;
#pragma unroll
        for (int u = 0; u < 3; u++) {
            int yy = y + u - 1;
            bool yv = (yy >= 0) && (yy < H);
            const float* grow = gch + yy * W;
            float v[4];
#pragma unroll
            for (int q = 0; q < 4; q++) {
                int xx = x + q - 1;
                v[q] = (yv && xx >= 0 && xx < W) ? grow[xx] : 0.0f;
            }
#pragma unroll
            for (int kx = 0; kx < 3; kx++) {
                u64 vA = pack2(v[kx], v[kx + 1]);
                const u64* wrow = &ws2[i * 9 + u * 3 + kx];
#pragma unroll
                for (int c = 0; c < 24; c++) {
                    acc[c] = fma2(vA, wrow[c * 72], acc[c]);
                }
            }
        }
    }

    float inv_scale = 1.0f / (aff_scale[0] + 1e-8f);

    // Affinity normalization for both pixels (TGASS).
    float a0[8], a1[8];
    float s0 = 0.0f, s1 = 0.0f;
#pragma unroll
    for (int k = 0; k < 8; k++) {
        float lo, hi;
        unpack2(acc[16 + k], lo, hi);
        a0[k] = tanhf(lo) * inv_scale;
        a1[k] = tanhf(hi) * inv_scale;
        s0 += fabsf(a0[k]);
        s1 += fabsf(a1[k]);
    }
    s0 += 1e-4f; if (s0 < 1.0f) s0 = 1.0f;
    s1 += 1e-4f; if (s1 < 1.0f) s1 = 1.0f;
    float i0 = 1.0f / s0, i1 = 1.0f / s1;
#pragma unroll
    for (int k = 0; k < 8; k++) { a0[k] *= i0; a1[k] *= i1; }

    // Encode + store plane-by-plane; <=2 u64 records live per pixel.
#pragma unroll
    for (int q = 0; q < 4; q++) {
        u64 r00, r01, r10, r11;
#pragma unroll
        for (int e = 0; e < 2; e++) {
            int k = 2 * q + e;
            int j = (k < 4) ? k : k + 1;
            float dy0, dy1, dx0, dx1;
            unpack2(acc[2 * k],     dy0, dy1);
            unpack2(acc[2 * k + 1], dx0, dx1);
            u64 rp0 = encode_tap(b, y, x,     j, dy0, dx0, a0[k]);
            u64 rp1 = encode_tap(b, y, x + 1, j, dy1, dx1, a1[k]);
            if (e == 0) { r00 = rp0; r10 = rp1; }
            else        { r01 = rp0; r11 = rp1; }
        }
        d_meta[q * NPX + p0] = make_uint4((unsigned)r00, (unsigned)(r00 >> 32),
                                          (unsigned)r01, (unsigned)(r01 >> 32));
        d_meta[q * NPX + p0 + 1] = make_uint4((unsigned)r10, (unsigned)(r10 >> 32),
                                              (unsigned)r11, (unsigned)(r11 >> 32));
    }
}

// ---------------------------------------------------------------------------
// One propagation step (frozen R5 shape: 1 px/thread, scalar gathers).
// Center affinity = 1 - sum(decoded tap affs): operator rows sum exactly to 1.
__device__ __forceinline__ void apply_tap(const float* __restrict__ gin,
                                          unsigned lo, unsigned hi,
                                          float& acc, float& asum) {
    u64 m = (u64)lo | ((u64)hi << 32);
    unsigned idx = (unsigned)(m & 0x1FFFFFull);
    float fy = (float)((unsigned)(m >> 21) & 0x1FFFu) * (1.0f / 8192.0f);
    float fx = (float)((unsigned)(m >> 34) & 0x1FFFu) * (1.0f / 8192.0f);
    float av = (float)((int)((unsigned)(m >> 47) & 0x1FFFFu) - 65536)
               * (1.0f / 32768.0f);
    const float* gp = gin + idx;
    float f00 = gp[0];
    float f01 = gp[1];
    float f10 = gp[WP];
    float f11 = gp[WP + 1];
    float top = fmaf(fx, f01 - f00, f00);
    float bot = fmaf(fx, f11 - f10, f10);
    acc  = fmaf(av, fmaf(fy, bot - top, top), acc);
    asum += av;
}

__global__ void iter_kernel(const float* __restrict__ conf,
                            float* __restrict__ out, int sel, int last) {
    int p = blockIdx.x * blockDim.x + threadIdx.x;
    if (p >= NPX) return;
    const float* __restrict__ gin = g_buf[sel];
    int b = p / HW;
    int r = p - b * HW;
    int y = r / W;
    int x = r - y * W;
    int center = (b * HP + y + PAD) * WP + (x + PAD);

    float acc = 0.0f, asum = 0.0f;
#pragma unroll
    for (int q = 0; q < 4; q++) {
        uint4 mm = d_meta[q * NPX + p];
        apply_tap(gin, mm.x, mm.y, acc, asum);
        apply_tap(gin, mm.z, mm.w, acc, asum);
    }
    float v = fmaf(1.0f - asum, gin[center], acc);
    if (last) out[p] = v;
    else      g_buf[sel ^ 1][center] = conf[p] * v;
}

// ---------------------------------------------------------------------------
extern "C" void kernel_launch(void* const* d_in, const int* in_sizes, int n_in,
                              void* d_out, int out_size) {
    const float* feat = (const float*)d_in[0];
    const float* guid = (const float*)d_in[1];
    const float* conf = (const float*)d_in[2];
    const float* w    = (const float*)d_in[3];
    const float* bia  = (const float*)d_in[4];
    const float* sc   = (const float*)d_in[5];
    float* out = (float*)d_out;

    const int thr = 256;
    zero_kernel<<<(2 * NPAD + thr - 1) / thr, thr>>>();
    init_kernel<<<(NPX + thr - 1) / thr, thr>>>(feat, conf);
    conv_meta_kernel<<<(NPX / 2 + thr - 1) / thr, thr>>>(guid, w, bia, sc);
    for (int t = 0; t < PROP; t++) {
        iter_kernel<<<(NPX + thr - 1) / thr, thr>>>(conf, out, t & 1, t == PROP - 1);
    }
}

// round 15
// speedup vs baseline: 1.4410x; 1.4410x over previous
#include <cuda_runtime.h>
#include <cuda_bf16.h>
#include <stdint.h>

// Problem constants
#define BB   4
#define H    352
#define W    1216
#define HW   (H*W)               // 428032
#define NPX  (BB*HW)             // 1712128 pixels (divisible by 4)
#define PAD  2
#define HP   (H + 2*PAD)         // 356
#define WP   (W + 2*PAD)         // 1220
#define NPAD (BB*HP*WP)          // 1737280 < 2^21
#define PROP 18

typedef unsigned long long u64;

// Packed tap record (u64):
//  [0,21)   : padded linear index of top-left corner
//  [21,34)  : fy  (13-bit fraction, /8192)
//  [34,47)  : fx  (13-bit fraction, /8192)
//  [47,64)  : aff (17-bit fixed point, (q-65536)/32768)
// Stored as 4 planes of uint4 (two taps per 16B record) for LDG.128.

// Fixed 1KB alignment: build-to-build link layout must not change the
// sector/L2 alignment of the gather-heavy buffers.
__device__ __align__(1024) float g_buf[2][NPAD];
__device__ __align__(1024) uint4 d_meta[4 * NPX];

// ---------------------------------------------------------------------------
// Packed fp32x2 helpers (Blackwell dual-rate fp32 path; FFMA2 only via PTX)
__device__ __forceinline__ u64 pack2(float lo, float hi) {
    u64 r; asm("mov.b64 %0, {%1, %2};" : "=l"(r) : "f"(lo), "f"(hi)); return r;
}
__device__ __forceinline__ void unpack2(u64 v, float& lo, float& hi) {
    asm("mov.b64 {%0, %1}, %2;" : "=f"(lo), "=f"(hi) : "l"(v));
}
__device__ __forceinline__ u64 fma2(u64 a, u64 b, u64 c) {
    u64 d; asm("fma.rn.f32x2 %0, %1, %2, %3;" : "=l"(d) : "l"(a), "l"(b), "l"(c));
    return d;
}

// ---------------------------------------------------------------------------
__global__ void zero_kernel() {
    int i = blockIdx.x * blockDim.x + threadIdx.x;
    if (i < 2 * NPAD) (&g_buf[0][0])[i] = 0.0f;
}

__global__ void init_kernel(const float* __restrict__ feat,
                            const float* __restrict__ conf) {
    int p = blockIdx.x * blockDim.x + threadIdx.x;
    if (p >= NPX) return;
    int b = p / HW;
    int r = p - b * HW;
    int y = r / W;
    int x = r - y * W;
    int pidx = (b * HP + y + PAD) * WP + (x + PAD);
    g_buf[0][pidx] = feat[p] * conf[p];
}

// ---------------------------------------------------------------------------
__device__ __forceinline__ u64 encode_tap(
        int b, int y, int x, int j, float dy, float dx, float aff)
{
    float ys = (float)(y + j / 3 - 1) + dy;
    float xs = (float)(x + j % 3 - 1) + dx;
    float y0f = floorf(ys);
    float x0f = floorf(xs);
    float fy = ys - y0f;
    float fx = xs - x0f;
    int iy = (int)fmaxf(fminf(y0f, 1.0e6f), -1.0e6f);
    int ix = (int)fmaxf(fminf(x0f, 1.0e6f), -1.0e6f);
    // clamp into padded box; out-of-image corners land on guaranteed zeros
    int yp = min(max(iy + PAD, 0), HP - 2);
    int xp = min(max(ix + PAD, 0), WP - 2);
    u64 idx = (u64)((b * HP + yp) * WP + xp);
    int fu = (int)(fy * 8192.0f + 0.5f); fu = min(max(fu, 0), 8191);
    int fv = (int)(fx * 8192.0f + 0.5f); fv = min(max(fv, 0), 8191);
    int qa = (int)floorf(aff * 32768.0f + 0.5f) + 65536;
    qa = min(max(qa, 0), 131071);
    return idx | ((u64)fu << 21) | ((u64)fv << 34) | ((u64)qa << 47);
}

// Conv(8 -> 24, 3x3, pad 1) via packed f32x2 FFMA2; 2 pixels / thread
// (one lane-pair). Register-lean epilogue: encode+store per plane.
__global__ __launch_bounds__(256)
void conv_meta_kernel(const float* __restrict__ guid,
                      const float* __restrict__ w_oa,
                      const float* __restrict__ b_oa,
                      const float* __restrict__ aff_scale) {
    __shared__ u64   ws2[1728];
    __shared__ float bs[24];
    for (int i = threadIdx.x; i < 1728; i += blockDim.x) {
        float w = w_oa[i];
        ws2[i] = pack2(w, w);
    }
    if (threadIdx.x < 24) bs[threadIdx.x] = b_oa[threadIdx.x];
    __syncthreads();

    int t  = blockIdx.x * blockDim.x + threadIdx.x;
    int p0 = 2 * t;
    if (p0 >= NPX) return;
    int b = p0 / HW;
    int r = p0 - b * HW;
    int y = r / W;
    int x = r - y * W;   // x even (W even): both px same row

    u64 acc[24];         // lane pair = (px0, px1)
#pragma unroll
    for (int c = 0; c < 24; c++) acc[c] = pack2(bs[c], bs[c]);

    const float* gb = guid + (size_t)b * 8 * HW;
    for (int i = 0; i < 8; i++) {
        const float* gch = gb + i * HW;
#pragma unroll
        for (int u = 0; u < 3; u++) {
            int yy = y + u - 1;
            bool yv = (yy >= 0) && (yy < H);
            const float* grow = gch + yy * W;
            float v[4];
#pragma unroll
            for (int q = 0; q < 4; q++) {
                int xx = x + q - 1;
                v[q] = (yv && xx >= 0 && xx < W) ? grow[xx] : 0.0f;
            }
#pragma unroll
            for (int kx = 0; kx < 3; kx++) {
                u64 vA = pack2(v[kx], v[kx + 1]);
                const u64* wrow = &ws2[i * 9 + u * 3 + kx];
#pragma unroll
                for (int c = 0; c < 24; c++) {
                    acc[c] = fma2(vA, wrow[c * 72], acc[c]);
                }
            }
        }
    }

    float inv_scale = 1.0f / (aff_scale[0] + 1e-8f);

    // Affinity normalization for both pixels (TGASS).
    float a0[8], a1[8];
    float s0 = 0.0f, s1 = 0.0f;
#pragma unroll
    for (int k = 0; k < 8; k++) {
        float lo, hi;
        unpack2(acc[16 + k], lo, hi);
        a0[k] = tanhf(lo) * inv_scale;
        a1[k] = tanhf(hi) * inv_scale;
        s0 += fabsf(a0[k]);
        s1 += fabsf(a1[k]);
    }
    s0 += 1e-4f; if (s0 < 1.0f) s0 = 1.0f;
    s1 += 1e-4f; if (s1 < 1.0f) s1 = 1.0f;
    float i0 = 1.0f / s0, i1 = 1.0f / s1;
#pragma unroll
    for (int k = 0; k < 8; k++) { a0[k] *= i0; a1[k] *= i1; }

    // Encode + store plane-by-plane; <=4 u64 records live at a time.
#pragma unroll
    for (int q = 0; q < 4; q++) {
        u64 r00, r01, r10, r11;
#pragma unroll
        for (int e = 0; e < 2; e++) {
            int k = 2 * q + e;
            int j = (k < 4) ? k : k + 1;
            float dy0, dy1, dx0, dx1;
            unpack2(acc[2 * k],     dy0, dy1);
            unpack2(acc[2 * k + 1], dx0, dx1);
            u64 rp0 = encode_tap(b, y, x,     j, dy0, dx0, a0[k]);
            u64 rp1 = encode_tap(b, y, x + 1, j, dy1, dx1, a1[k]);
            if (e == 0) { r00 = rp0; r10 = rp1; }
            else        { r01 = rp0; r11 = rp1; }
        }
        d_meta[q * NPX + p0] = make_uint4((unsigned)r00, (unsigned)(r00 >> 32),
                                          (unsigned)r01, (unsigned)(r01 >> 32));
        d_meta[q * NPX + p0 + 1] = make_uint4((unsigned)r10, (unsigned)(r10 >> 32),
                                              (unsigned)r11, (unsigned)(r11 >> 32));
    }
}

// ---------------------------------------------------------------------------
// One propagation step (frozen R5/R11 shape: 1 px/thread, scalar gathers).
// Center affinity = 1 - sum(decoded tap affs): operator rows sum exactly to 1.
__device__ __forceinline__ void apply_tap(const float* __restrict__ gin,
                                          unsigned lo, unsigned hi,
                                          float& acc, float& asum) {
    u64 m = (u64)lo | ((u64)hi << 32);
    unsigned idx = (unsigned)(m & 0x1FFFFFull);
    float fy = (float)((unsigned)(m >> 21) & 0x1FFFu) * (1.0f / 8192.0f);
    float fx = (float)((unsigned)(m >> 34) & 0x1FFFu) * (1.0f / 8192.0f);
    float av = (float)((int)((unsigned)(m >> 47) & 0x1FFFFu) - 65536)
               * (1.0f / 32768.0f);
    const float* gp = gin + idx;
    float f00 = gp[0];
    float f01 = gp[1];
    float f10 = gp[WP];
    float f11 = gp[WP + 1];
    float top = fmaf(fx, f01 - f00, f00);
    float bot = fmaf(fx, f11 - f10, f10);
    acc  = fmaf(av, fmaf(fy, bot - top, top), acc);
    asum += av;
}

__global__ void iter_kernel(const float* __restrict__ conf,
                            float* __restrict__ out, int sel, int last) {
    int p = blockIdx.x * blockDim.x + threadIdx.x;
    if (p >= NPX) return;
    const float* __restrict__ gin = g_buf[sel];
    int b = p / HW;
    int r = p - b * HW;
    int y = r / W;
    int x = r - y * W;
    int center = (b * HP + y + PAD) * WP + (x + PAD);

    float acc = 0.0f, asum = 0.0f;
#pragma unroll
    for (int q = 0; q < 4; q++) {
        uint4 mm = d_meta[q * NPX + p];
        apply_tap(gin, mm.x, mm.y, acc, asum);
        apply_tap(gin, mm.z, mm.w, acc, asum);
    }
    float v = fmaf(1.0f - asum, gin[center], acc);
    if (last) out[p] = v;
    else      g_buf[sel ^ 1][center] = conf[p] * v;
}

// ---------------------------------------------------------------------------
extern "C" void kernel_launch(void* const* d_in, const int* in_sizes, int n_in,
                              void* d_out, int out_size) {
    const float* feat = (const float*)d_in[0];
    const float* guid = (const float*)d_in[1];
    const float* conf = (const float*)d_in[2];
    const float* w    = (const float*)d_in[3];
    const float* bia  = (const float*)d_in[4];
    const float* sc   = (const float*)d_in[5];
    float* out = (float*)d_out;

    const int thr = 256;
    zero_kernel<<<(2 * NPAD + thr - 1) / thr, thr>>>();
    init_kernel<<<(NPX + thr - 1) / thr, thr>>>(feat, conf);
    conv_meta_kernel<<<(NPX / 2 + thr - 1) / thr, thr>>>(guid, w, bia, sc);
    for (int t = 0; t < PROP; t++) {
        iter_kernel<<<(NPX + thr - 1) / thr, thr>>>(conf, out, t & 1, t == PROP - 1);
    }
}

// round 16
// speedup vs baseline: 1.5582x; 1.0813x over previous
#include <cuda_runtime.h>
#include <cuda_bf16.h>
#include <stdint.h>

// Problem constants
#define BB   4
#define H    352
#define W    1216
#define HW   (H*W)               // 428032
#define NPX  (BB*HW)             // 1712128 pixels (divisible by 4)
#define PAD  2
#define HP   (H + 2*PAD)         // 356
#define WP   (W + 2*PAD)         // 1220
#define NPAD (BB*HP*WP)          // 1737280 < 2^21
#define PROP 18

typedef unsigned long long u64;

// Packed tap record (u64):
//  [0,21)   : padded linear index of top-left corner
//  [21,34)  : fy  (13-bit fraction, /8192)
//  [34,47)  : fx  (13-bit fraction, /8192)
//  [47,64)  : aff (17-bit fixed point, (q-65536)/32768)
// Stored as 4 planes of uint4 (two taps per 16B record) for LDG.128.

// Fixed 1KB alignment: build-to-build link layout must not change the
// sector/L2 alignment of the gather-heavy buffers.
__device__ __align__(1024) float g_buf[2][NPAD];
__device__ __align__(1024) uint4 d_meta[4 * NPX];

// ---------------------------------------------------------------------------
// Packed fp32x2 helpers (Blackwell dual-rate fp32 path; FFMA2 only via PTX)
__device__ __forceinline__ u64 pack2(float lo, float hi) {
    u64 r; asm("mov.b64 %0, {%1, %2};" : "=l"(r) : "f"(lo), "f"(hi)); return r;
}
__device__ __forceinline__ void unpack2(u64 v, float& lo, float& hi) {
    asm("mov.b64 {%0, %1}, %2;" : "=f"(lo), "=f"(hi) : "l"(v));
}
__device__ __forceinline__ u64 fma2(u64 a, u64 b, u64 c) {
    u64 d; asm("fma.rn.f32x2 %0, %1, %2, %3;" : "=l"(d) : "l"(a), "l"(b), "l"(c));
    return d;
}

// ---------------------------------------------------------------------------
__global__ void zero_kernel() {
    int i = blockIdx.x * blockDim.x + threadIdx.x;
    if (i < 2 * NPAD) (&g_buf[0][0])[i] = 0.0f;
}

__global__ void init_kernel(const float* __restrict__ feat,
                            const float* __restrict__ conf) {
    int p = blockIdx.x * blockDim.x + threadIdx.x;
    if (p >= NPX) return;
    int b = p / HW;
    int r = p - b * HW;
    int y = r / W;
    int x = r - y * W;
    int pidx = (b * HP + y + PAD) * WP + (x + PAD);
    g_buf[0][pidx] = feat[p] * conf[p];
}

// ---------------------------------------------------------------------------
__device__ __forceinline__ u64 encode_tap(
        int b, int y, int x, int j, float dy, float dx, float aff)
{
    float ys = (float)(y + j / 3 - 1) + dy;
    float xs = (float)(x + j % 3 - 1) + dx;
    float y0f = floorf(ys);
    float x0f = floorf(xs);
    float fy = ys - y0f;
    float fx = xs - x0f;
    int iy = (int)fmaxf(fminf(y0f, 1.0e6f), -1.0e6f);
    int ix = (int)fmaxf(fminf(x0f, 1.0e6f), -1.0e6f);
    // clamp into padded box; out-of-image corners land on guaranteed zeros
    int yp = min(max(iy + PAD, 0), HP - 2);
    int xp = min(max(ix + PAD, 0), WP - 2);
    u64 idx = (u64)((b * HP + yp) * WP + xp);
    int fu = (int)(fy * 8192.0f + 0.5f); fu = min(max(fu, 0), 8191);
    int fv = (int)(fx * 8192.0f + 0.5f); fv = min(max(fv, 0), 8191);
    int qa = (int)floorf(aff * 32768.0f + 0.5f) + 65536;
    qa = min(max(qa, 0), 131071);
    return idx | ((u64)fu << 21) | ((u64)fv << 34) | ((u64)qa << 47);
}

// TGASS normalization + encode + store for one f32x2 pixel-pair lane.
__device__ __forceinline__ void epilogue_pair(const u64* acc, int p0,
                                              int b, int y, int x,
                                              float inv_scale) {
    float a0[8], a1[8];
    float s0 = 0.0f, s1 = 0.0f;
#pragma unroll
    for (int k = 0; k < 8; k++) {
        float lo, hi;
        unpack2(acc[16 + k], lo, hi);
        a0[k] = tanhf(lo) * inv_scale;
        a1[k] = tanhf(hi) * inv_scale;
        s0 += fabsf(a0[k]);
        s1 += fabsf(a1[k]);
    }
    s0 += 1e-4f; if (s0 < 1.0f) s0 = 1.0f;
    s1 += 1e-4f; if (s1 < 1.0f) s1 = 1.0f;
    float i0 = 1.0f / s0, i1 = 1.0f / s1;
#pragma unroll
    for (int k = 0; k < 8; k++) { a0[k] *= i0; a1[k] *= i1; }

#pragma unroll
    for (int q = 0; q < 4; q++) {
        u64 r00, r01, r10, r11;
#pragma unroll
        for (int e = 0; e < 2; e++) {
            int k = 2 * q + e;
            int j = (k < 4) ? k : k + 1;
            float dy0, dy1, dx0, dx1;
            unpack2(acc[2 * k],     dy0, dy1);
            unpack2(acc[2 * k + 1], dx0, dx1);
            u64 rp0 = encode_tap(b, y, x,     j, dy0, dx0, a0[k]);
            u64 rp1 = encode_tap(b, y, x + 1, j, dy1, dx1, a1[k]);
            if (e == 0) { r00 = rp0; r10 = rp1; }
            else        { r01 = rp0; r11 = rp1; }
        }
        d_meta[q * NPX + p0] = make_uint4((unsigned)r00, (unsigned)(r00 >> 32),
                                          (unsigned)r01, (unsigned)(r01 >> 32));
        d_meta[q * NPX + p0 + 1] = make_uint4((unsigned)r10, (unsigned)(r10 >> 32),
                                              (unsigned)r11, (unsigned)(r11 >> 32));
    }
}

// Conv(8 -> 24, 3x3, pad 1) via packed f32x2 FFMA2; 4 pixels / thread
// (two lane-pairs sharing each weight load). Weights in smem transposed to
// point-major [pt][c] as pre-duplicated (w,w) u64 pairs: one LDS.128 yields
// TWO channels' weights -> 864 LDS.128/thread instead of 1728 LDS.64.
__global__ __launch_bounds__(128)
void conv_meta_kernel(const float* __restrict__ guid,
                      const float* __restrict__ w_oa,
                      const float* __restrict__ b_oa,
                      const float* __restrict__ aff_scale) {
    __shared__ __align__(16) double2 wsd[864];   // [pt*12 + c/2]
    __shared__ float bs[24];
    for (int idx = threadIdx.x; idx < 864; idx += blockDim.x) {
        int pt = idx / 12;
        int c  = 2 * (idx - pt * 12);
        float w0 = w_oa[c * 72 + pt];
        float w1 = w_oa[(c + 1) * 72 + pt];
        wsd[idx] = make_double2(__longlong_as_double(pack2(w0, w0)),
                                __longlong_as_double(pack2(w1, w1)));
    }
    if (threadIdx.x < 24) bs[threadIdx.x] = b_oa[threadIdx.x];
    __syncthreads();

    int t  = blockIdx.x * blockDim.x + threadIdx.x;
    int p0 = 4 * t;
    if (p0 >= NPX) return;
    int b = p0 / HW;
    int r = p0 - b * HW;
    int y = r / W;
    int x = r - y * W;   // x % 4 == 0 (W divisible by 4): 4 px same row

    u64 accA[24], accB[24];   // accA = (px0,px1), accB = (px2,px3)
#pragma unroll
    for (int c = 0; c < 24; c++) {
        u64 bb2 = pack2(bs[c], bs[c]);
        accA[c] = bb2;
        accB[c] = bb2;
    }

    const float* gb = guid + (size_t)b * 8 * HW;
    for (int i = 0; i < 8; i++) {
        const float* gch = gb + i * HW;
#pragma unroll
        for (int u = 0; u < 3; u++) {
            int yy = y + u - 1;
            bool yv = (yy >= 0) && (yy < H);
            const float* grow = gch + yy * W;
            float v[6];
#pragma unroll
            for (int q = 0; q < 6; q++) {
                int xx = x + q - 1;
                v[q] = (yv && xx >= 0 && xx < W) ? grow[xx] : 0.0f;
            }
#pragma unroll
            for (int kx = 0; kx < 3; kx++) {
                u64 vA = pack2(v[kx],     v[kx + 1]);
                u64 vB = pack2(v[kx + 2], v[kx + 3]);
                const double2* wrow = &wsd[(i * 9 + u * 3 + kx) * 12];
#pragma unroll
                for (int c2 = 0; c2 < 12; c2++) {
                    double2 wd = wrow[c2];              // LDS.128 broadcast
                    u64 wa = __double_as_longlong(wd.x);
                    u64 wb = __double_as_longlong(wd.y);
                    accA[2 * c2]     = fma2(vA, wa, accA[2 * c2]);
                    accB[2 * c2]     = fma2(vB, wa, accB[2 * c2]);
                    accA[2 * c2 + 1] = fma2(vA, wb, accA[2 * c2 + 1]);
                    accB[2 * c2 + 1] = fma2(vB, wb, accB[2 * c2 + 1]);
                }
            }
        }
    }

    float inv_scale = 1.0f / (aff_scale[0] + 1e-8f);
    epilogue_pair(accA, p0,     b, y, x,     inv_scale);
    epilogue_pair(accB, p0 + 2, b, y, x + 2, inv_scale);
}

// ---------------------------------------------------------------------------
// One propagation step (frozen R5/R11/R15 shape: 1 px/thread, scalar gathers).
// Center affinity = 1 - sum(decoded tap affs): operator rows sum exactly to 1.
__device__ __forceinline__ void apply_tap(const float* __restrict__ gin,
                                          unsigned lo, unsigned hi,
                                          float& acc, float& asum) {
    u64 m = (u64)lo | ((u64)hi << 32);
    unsigned idx = (unsigned)(m & 0x1FFFFFull);
    float fy = (float)((unsigned)(m >> 21) & 0x1FFFu) * (1.0f / 8192.0f);
    float fx = (float)((unsigned)(m >> 34) & 0x1FFFu) * (1.0f / 8192.0f);
    float av = (float)((int)((unsigned)(m >> 47) & 0x1FFFFu) - 65536)
               * (1.0f / 32768.0f);
    const float* gp = gin + idx;
    float f00 = gp[0];
    float f01 = gp[1];
    float f10 = gp[WP];
    float f11 = gp[WP + 1];
    float top = fmaf(fx, f01 - f00, f00);
    float bot = fmaf(fx, f11 - f10, f10);
    acc  = fmaf(av, fmaf(fy, bot - top, top), acc);
    asum += av;
}

__global__ void iter_kernel(const float* __restrict__ conf,
                            float* __restrict__ out, int sel, int last) {
    int p = blockIdx.x * blockDim.x + threadIdx.x;
    if (p >= NPX) return;
    const float* __restrict__ gin = g_buf[sel];
    int b = p / HW;
    int r = p - b * HW;
    int y = r / W;
    int x = r - y * W;
    int center = (b * HP + y + PAD) * WP + (x + PAD);

    float acc = 0.0f, asum = 0.0f;
#pragma unroll
    for (int q = 0; q < 4; q++) {
        uint4 mm = d_meta[q * NPX + p];
        apply_tap(gin, mm.x, mm.y, acc, asum);
        apply_tap(gin, mm.z, mm.w, acc, asum);
    }
    float v = fmaf(1.0f - asum, gin[center], acc);
    if (last) out[p] = v;
    else      g_buf[sel ^ 1][center] = conf[p] * v;
}

// ---------------------------------------------------------------------------
extern "C" void kernel_launch(void* const* d_in, const int* in_sizes, int n_in,
                              void* d_out, int out_size) {
    const float* feat = (const float*)d_in[0];
    const float* guid = (const float*)d_in[1];
    const float* conf = (const float*)d_in[2];
    const float* w    = (const float*)d_in[3];
    const float* bia  = (const float*)d_in[4];
    const float* sc   = (const float*)d_in[5];
    float* out = (float*)d_out;

    const int thr = 256;
    zero_kernel<<<(2 * NPAD + thr - 1) / thr, thr>>>();
    init_kernel<<<(NPX + thr - 1) / thr, thr>>>(feat, conf);
    conv_meta_kernel<<<(NPX / 4 + 127) / 128, 128>>>(guid, w, bia, sc);
    for (int t = 0; t < PROP; t++) {
        iter_kernel<<<(NPX + thr - 1) / thr, thr>>>(conf, out, t & 1, t == PROP - 1);
    }
}